// round 2
// baseline (speedup 1.0000x reference)
#include <cuda_runtime.h>

#define H 256
#define W 256
#define D 256
#define D4 64           // D / 4 (float4 lanes)
#define SEG 128         // split length for both scan dimensions
#define N_BOXES 2048

// 64 MB SAT scratch (float4 view) + 1 MB of segment-0 row totals.
__device__ float4 g_sat[(size_t)H * W * D4];
__device__ float4 g_rowtot[(size_t)H * D4];   // satA[h][SEG-1][d] (row prefix through w=127)

__device__ __forceinline__ void acc4(float4& a, const float4 v) {
    a.x += v.x; a.y += v.y; a.z += v.z; a.w += v.w;
}

// ---------------------------------------------------------------------------
// Pass A: prefix along W, split into 2 independent 128-wide segments.
// thread -> (h, seg, d4); consecutive threads = consecutive d4 (coalesced 16B).
// Segment 0 also exports its final accumulator as the row-total fixup.
// ---------------------------------------------------------------------------
__global__ void __launch_bounds__(256) pass_a(const float4* __restrict__ feat) {
    int t   = blockIdx.x * blockDim.x + threadIdx.x;
    int d4  = t & (D4 - 1);
    int seg = (t >> 6) & 1;
    int h   = t >> 7;

    size_t base = ((size_t)h * W + seg * SEG) * D4 + d4;
    const float4* __restrict__ src = feat + base;
    float4* __restrict__ dst = g_sat + base;

    float4 acc = make_float4(0.f, 0.f, 0.f, 0.f);
#pragma unroll 8
    for (int w = 0; w < SEG; ++w) {
        float4 v = src[(size_t)w * D4];
        acc4(acc, v);
        dst[(size_t)w * D4] = acc;
    }
    if (seg == 0) g_rowtot[(size_t)h * D4 + d4] = acc;
}

// ---------------------------------------------------------------------------
// Pass B: prefix along H (in place), split into 2 independent 128-tall
// segments. Threads with w >= 128 first complete the row prefix by adding the
// segment-0 row total (g_rowtot: 1 MB, L2/L1 resident, broadcast across w).
// Output = column-partial SAT per h-segment; the h fixup happens in gather.
// ---------------------------------------------------------------------------
__global__ void __launch_bounds__(256) pass_b() {
    int t   = blockIdx.x * blockDim.x + threadIdx.x;
    int d4  = t & (D4 - 1);
    int seg = (t >> 6) & 1;
    int w   = t >> 7;

    int h0 = seg * SEG;
    bool fixup = (w >= SEG);
    float4* __restrict__ p   = g_sat + ((size_t)h0 * W + w) * D4 + d4;
    const float4* __restrict__ fix = g_rowtot + (size_t)h0 * D4 + d4;

    float4 acc = make_float4(0.f, 0.f, 0.f, 0.f);
#pragma unroll 8
    for (int i = 0; i < SEG; ++i) {
        float4 v = p[(size_t)i * W * D4];
        if (fixup) acc4(v, fix[(size_t)i * D4]);
        acc4(acc, v);
        p[(size_t)i * W * D4] = acc;
    }
}

// Full SAT value at (r, c): pass-B output plus the h-segment fixup
// (row SEG-1 is column-complete for segment 0 and row-complete everywhere).
__device__ __forceinline__ float4 satval(int r, int c, int d4) {
    float4 v = g_sat[((size_t)r * W + c) * D4 + d4];
    if (r >= SEG) acc4(v, g_sat[((size_t)(SEG - 1) * W + c) * D4 + d4]);
    return v;
}

// ---------------------------------------------------------------------------
// Gather: 4 boxes per block, 64 float4 lanes per box. <= 8 corner loads,
// all L2 hits (SAT is L2-resident after pass B).
// ---------------------------------------------------------------------------
__global__ void __launch_bounds__(256) roi_gather(const float* __restrict__ boxes,
                                                  float4* __restrict__ out) {
    int n  = blockIdx.x * 4 + (threadIdx.x >> 6);
    int d4 = threadIdx.x & (D4 - 1);

    float x1 = boxes[n * 4 + 0];
    float y1 = boxes[n * 4 + 1];
    float x2 = boxes[n * 4 + 2];
    float y2 = boxes[n * 4 + 3];

    // _bounds: lo = max(0, floor(lo_f*256)); hi = rint(hi_f*256 + 0.5)
    //          hi = min(256, max(lo+1, hi)).  No FMA contraction (match jax).
    int clo = max(0, (int)floorf(__fmul_rn(x1, 256.0f)));
    int chi = (int)rintf(__fadd_rn(__fmul_rn(x2, 256.0f), 0.5f));
    chi = min(W, max(clo + 1, chi));

    int rlo = max(0, (int)floorf(__fmul_rn(y1, 256.0f)));
    int rhi = (int)rintf(__fadd_rn(__fmul_rn(y2, 256.0f), 0.5f));
    rhi = min(H, max(rlo + 1, rhi));

    float4 s = satval(rhi - 1, chi - 1, d4);
    if (rlo > 0) {
        float4 a = satval(rlo - 1, chi - 1, d4);
        s.x -= a.x; s.y -= a.y; s.z -= a.z; s.w -= a.w;
    }
    if (clo > 0) {
        float4 b = satval(rhi - 1, clo - 1, d4);
        s.x -= b.x; s.y -= b.y; s.z -= b.z; s.w -= b.w;
        if (rlo > 0) {
            float4 c = satval(rlo - 1, clo - 1, d4);
            acc4(s, c);
        }
    }

    float inv = 1.0f / (float)((rhi - rlo) * (chi - clo));
    s.x *= inv; s.y *= inv; s.z *= inv; s.w *= inv;
    out[(size_t)n * D4 + d4] = s;
}

extern "C" void kernel_launch(void* const* d_in, const int* in_sizes, int n_in,
                              void* d_out, int out_size) {
    const float4* feat  = (const float4*)d_in[0];   // (256,256,256) fp32
    const float*  boxes = (const float*)d_in[1];    // (2048,4) fp32
    float4* out = (float4*)d_out;                   // (2048,256) fp32

    pass_a<<<(H * 2 * D4) / 256, 256>>>(feat);
    pass_b<<<(W * 2 * D4) / 256, 256>>>();
    roi_gather<<<N_BOXES / 4, 256>>>(boxes, out);
}

// round 3
// speedup vs baseline: 1.7925x; 1.7925x over previous
#include <cuda_runtime.h>

#define H 256
#define W 256
#define D4 64            // 256 channels / 4 (float4 lanes)
#define NSEG 8           // segments per scan dimension
#define SEGLEN 32        // 256 / NSEG
#define N_BOXES 2048

// 64 MB SAT scratch + small fixup buffers (2 MB each).
__device__ float4 g_sat[(size_t)H * W * D4];
__device__ float4 g_tot_a[(size_t)H * NSEG * D4];    // row-segment totals
__device__ float4 g_rowfix[(size_t)H * NSEG * D4];   // exclusive prefix of tot_a over seg
__device__ float4 g_tot_b[(size_t)NSEG * W * D4];    // col-segment totals
__device__ float4 g_colfix[(size_t)NSEG * W * D4];   // exclusive prefix of tot_b over seg

__device__ __forceinline__ void acc4(float4& a, const float4 v) {
    a.x += v.x; a.y += v.y; a.z += v.z; a.w += v.w;
}

// ---------------------------------------------------------------------------
// Pass A: partial prefix along W in 8 segments of 32.
// t -> d4 (64) | seg (8) | h (256) : 131072 threads, 512 blocks.
// ---------------------------------------------------------------------------
__global__ void __launch_bounds__(256) pass_a(const float4* __restrict__ feat) {
    int t   = blockIdx.x * blockDim.x + threadIdx.x;
    int d4  = t & (D4 - 1);
    int seg = (t >> 6) & (NSEG - 1);
    int h   = t >> 9;

    size_t base = ((size_t)h * W + seg * SEGLEN) * D4 + d4;
    const float4* __restrict__ src = feat + base;
    float4* __restrict__ dst = g_sat + base;

    float4 acc = make_float4(0.f, 0.f, 0.f, 0.f);
#pragma unroll 8
    for (int w = 0; w < SEGLEN; ++w) {
        float4 v = src[(size_t)w * D4];
        acc4(acc, v);
        dst[(size_t)w * D4] = acc;
    }
    g_tot_a[((size_t)h * NSEG + seg) * D4 + d4] = acc;
}

// Exclusive prefix of row-segment totals (<=7 L2 loads per thread).
__global__ void __launch_bounds__(256) fix_a() {
    int t   = blockIdx.x * blockDim.x + threadIdx.x;
    int d4  = t & (D4 - 1);
    int seg = (t >> 6) & (NSEG - 1);
    int h   = t >> 9;

    float4 acc = make_float4(0.f, 0.f, 0.f, 0.f);
    for (int s = 0; s < seg; ++s)
        acc4(acc, g_tot_a[((size_t)h * NSEG + s) * D4 + d4]);
    g_rowfix[((size_t)h * NSEG + seg) * D4 + d4] = acc;
}

// ---------------------------------------------------------------------------
// Pass B: complete the row prefix (add rowfix) and do a partial prefix along
// H in 8 segments of 32, in place. t -> d4 | seg | w : 131072 threads.
// ---------------------------------------------------------------------------
__global__ void __launch_bounds__(256) pass_b() {
    int t   = blockIdx.x * blockDim.x + threadIdx.x;
    int d4  = t & (D4 - 1);
    int seg = (t >> 6) & (NSEG - 1);
    int w   = t >> 9;

    int h0 = seg * SEGLEN;
    int wseg = w >> 5;                         // which W-segment this column is in
    float4* __restrict__ p = g_sat + ((size_t)h0 * W + w) * D4 + d4;
    const float4* __restrict__ rf =
        g_rowfix + ((size_t)h0 * NSEG + wseg) * D4 + d4;

    float4 acc = make_float4(0.f, 0.f, 0.f, 0.f);
#pragma unroll 8
    for (int i = 0; i < SEGLEN; ++i) {
        float4 v = p[(size_t)i * W * D4];
        acc4(v, rf[(size_t)i * NSEG * D4]);
        acc4(acc, v);
        p[(size_t)i * W * D4] = acc;
    }
    g_tot_b[((size_t)seg * W + w) * D4 + d4] = acc;
}

// Exclusive prefix of column-segment totals.
__global__ void __launch_bounds__(256) fix_b() {
    int t   = blockIdx.x * blockDim.x + threadIdx.x;
    int d4  = t & (D4 - 1);
    int w   = (t >> 6) & (W - 1);
    int seg = t >> 14;

    float4 acc = make_float4(0.f, 0.f, 0.f, 0.f);
    for (int s = 0; s < seg; ++s)
        acc4(acc, g_tot_b[((size_t)s * W + w) * D4 + d4]);
    g_colfix[((size_t)seg * W + w) * D4 + d4] = acc;
}

// Full SAT value: partial + column-segment fixup (2 loads, L2-hit).
__device__ __forceinline__ float4 satval(int r, int c, int d4) {
    float4 v = g_sat[((size_t)r * W + c) * D4 + d4];
    acc4(v, g_colfix[((size_t)(r >> 5) * W + c) * D4 + d4]);
    return v;
}

// ---------------------------------------------------------------------------
// Gather: 4 boxes per block, 64 float4 lanes per box, <=8 corner loads.
// ---------------------------------------------------------------------------
__global__ void __launch_bounds__(256) roi_gather(const float* __restrict__ boxes,
                                                  float4* __restrict__ out) {
    int n  = blockIdx.x * 4 + (threadIdx.x >> 6);
    int d4 = threadIdx.x & (D4 - 1);

    float x1 = boxes[n * 4 + 0];
    float y1 = boxes[n * 4 + 1];
    float x2 = boxes[n * 4 + 2];
    float y2 = boxes[n * 4 + 3];

    // _bounds: lo = max(0, floor(lo_f*256)); hi = rint(hi_f*256 + 0.5)
    //          hi = min(256, max(lo+1, hi)).  No FMA contraction (match jax).
    int clo = max(0, (int)floorf(__fmul_rn(x1, 256.0f)));
    int chi = (int)rintf(__fadd_rn(__fmul_rn(x2, 256.0f), 0.5f));
    chi = min(W, max(clo + 1, chi));

    int rlo = max(0, (int)floorf(__fmul_rn(y1, 256.0f)));
    int rhi = (int)rintf(__fadd_rn(__fmul_rn(y2, 256.0f), 0.5f));
    rhi = min(H, max(rlo + 1, rhi));

    float4 s = satval(rhi - 1, chi - 1, d4);
    if (rlo > 0) {
        float4 a = satval(rlo - 1, chi - 1, d4);
        s.x -= a.x; s.y -= a.y; s.z -= a.z; s.w -= a.w;
    }
    if (clo > 0) {
        float4 b = satval(rhi - 1, clo - 1, d4);
        s.x -= b.x; s.y -= b.y; s.z -= b.z; s.w -= b.w;
        if (rlo > 0) {
            float4 c = satval(rlo - 1, clo - 1, d4);
            acc4(s, c);
        }
    }

    float inv = 1.0f / (float)((rhi - rlo) * (chi - clo));
    s.x *= inv; s.y *= inv; s.z *= inv; s.w *= inv;
    out[(size_t)n * D4 + d4] = s;
}

extern "C" void kernel_launch(void* const* d_in, const int* in_sizes, int n_in,
                              void* d_out, int out_size) {
    const float4* feat  = (const float4*)d_in[0];   // (256,256,256) fp32
    const float*  boxes = (const float*)d_in[1];    // (2048,4) fp32
    float4* out = (float4*)d_out;                   // (2048,256) fp32

    const int N = H * NSEG * D4;                    // 131072 threads per pass
    pass_a<<<N / 256, 256>>>(feat);
    fix_a <<<N / 256, 256>>>();
    pass_b<<<N / 256, 256>>>();
    fix_b <<<N / 256, 256>>>();
    roi_gather<<<N_BOXES / 4, 256>>>(boxes, out);
}

// round 4
// speedup vs baseline: 1.8621x; 1.0388x over previous
#include <cuda_runtime.h>

#define HH 256
#define WW 256
#define D4 64            // 256 channels as float4
#define NB 2048
#define RS 528           // smem row stride in 32-bit words: 528 % 32 == 16

// 64 MB tile-partial SAT + cum tables (2MB + 2MB + 64KB), all L2-friendly.
__device__ float4 g_part[(size_t)HH * WW * D4];
__device__ float4 g_rowcum[8 * 8 * 32 * D4];   // [ti][tj][r][d4]
__device__ float4 g_colcum[8 * 8 * 32 * D4];   // [ti][tj][c][d4]
__device__ float4 g_blockcum[8 * 8 * D4];      // [ti][tj][d4]

__device__ __forceinline__ void acc4(float4& a, const float4 v) {
    a.x += v.x; a.y += v.y; a.z += v.z; a.w += v.w;
}

// ---------------------------------------------------------------------------
// Main kernel: per-block tile = 32 rows x 32 cols x 4 float4 (16 channels).
// Grid = 8 x 8 tiles x 16 channel-groups = 1024 blocks.
// Stage gmem->smem (coalesced 64B chunks), row-scan + col-scan in smem
// (conflict-free: bank = kw + 16*((r+c)&1) patterns), unstage to g_part.
// ---------------------------------------------------------------------------
__global__ void __launch_bounds__(256, 2) sat_tile(const float4* __restrict__ feat) {
    extern __shared__ float sm[];
    int b    = blockIdx.x;
    int dgrp = b & 15;
    int tj   = (b >> 4) & 7;
    int ti   = b >> 7;
    int t    = threadIdx.x;
    int h0 = ti * 32, w0 = tj * 32, d0 = dgrp * 4;

    // Phase 1: stage. thread -> (d4'=t&3, w'=(t>>2)&31, rh=t>>7), 16 rows each.
    {
        int d4p = t & 3;
        int wp  = (t >> 2) & 31;
        int rh  = t >> 7;
        const float4* __restrict__ src =
            feat + ((size_t)h0 * WW + w0 + wp) * D4 + d0 + d4p;
#pragma unroll
        for (int rp = 0; rp < 16; ++rp) {
            int r = rh * 16 + rp;
            float4 v = src[(size_t)r * WW * D4];
            *reinterpret_cast<float4*>(&sm[r * RS + wp * 16 + d4p * 4]) = v;
        }
    }
    __syncthreads();

    // Phase 2: row scan (over c). unit = (row, word). 512 units, 2 per thread.
    {
        int kw = t & 15;
        int r0 = t >> 4;           // 0..15, second unit at r0+16
        float a0 = 0.f, a1 = 0.f;
#pragma unroll
        for (int c = 0; c < 32; ++c) {
            int i0 = r0 * RS + c * 16 + kw;
            int i1 = (r0 + 16) * RS + c * 16 + kw;
            a0 += sm[i0]; sm[i0] = a0;
            a1 += sm[i1]; sm[i1] = a1;
        }
    }
    __syncthreads();

    // Phase 3: col scan (over r). unit = (col, word).
    {
        int kw = t & 15;
        int c0 = t >> 4;
        float a0 = 0.f, a1 = 0.f;
#pragma unroll
        for (int r = 0; r < 32; ++r) {
            int i0 = r * RS + c0 * 16 + kw;
            int i1 = r * RS + (c0 + 16) * 16 + kw;
            a0 += sm[i0]; sm[i0] = a0;
            a1 += sm[i1]; sm[i1] = a1;
        }
    }
    __syncthreads();

    // Phase 4: unstage tile-partial SAT to g_part (same mapping as stage).
    {
        int d4p = t & 3;
        int wp  = (t >> 2) & 31;
        int rh  = t >> 7;
        float4* __restrict__ dst =
            g_part + ((size_t)h0 * WW + w0 + wp) * D4 + d0 + d4p;
#pragma unroll
        for (int rp = 0; rp < 16; ++rp) {
            int r = rh * 16 + rp;
            dst[(size_t)r * WW * D4] =
                *reinterpret_cast<float4*>(&sm[r * RS + wp * 16 + d4p * 4]);
        }
    }
}

// ---------------------------------------------------------------------------
// Fixups: one kernel, three jobs (rowcum / colcum / blockcum), reading tile
// edges directly out of g_part. Unconditional loads (MLP) + predicated adds.
// ---------------------------------------------------------------------------
__global__ void __launch_bounds__(256) fixups() {
    int flat = blockIdx.x * 256 + threadIdx.x;
    if (flat < 131072) {                       // rowcum: left strip sums at row r
        int d4 = flat & 63, r = (flat >> 6) & 31, tj = (flat >> 11) & 7, ti = flat >> 14;
        float4 acc = make_float4(0.f, 0.f, 0.f, 0.f);
#pragma unroll
        for (int s = 0; s < 7; ++s) {
            float4 v = g_part[((size_t)(ti * 32 + r) * WW + s * 32 + 31) * D4 + d4];
            if (s < tj) acc4(acc, v);
        }
        g_rowcum[((ti * 8 + tj) * 32 + r) * 64 + d4] = acc;
    } else if (flat < 262144) {                // colcum: above strip sums at col c
        int f = flat - 131072;
        int d4 = f & 63, c = (f >> 6) & 31, tj = (f >> 11) & 7, ti = f >> 14;
        float4 acc = make_float4(0.f, 0.f, 0.f, 0.f);
#pragma unroll
        for (int s = 0; s < 7; ++s) {
            float4 v = g_part[((size_t)(s * 32 + 31) * WW + tj * 32 + c) * D4 + d4];
            if (s < ti) acc4(acc, v);
        }
        g_colcum[((ti * 8 + tj) * 32 + c) * 64 + d4] = acc;
    } else {                                   // blockcum: 2D prefix of tile totals
        int f = flat - 262144;
        int d4 = f & 63, tj = (f >> 6) & 7, ti = f >> 9;
        float4 acc = make_float4(0.f, 0.f, 0.f, 0.f);
#pragma unroll
        for (int si = 0; si < 7; ++si)
#pragma unroll
            for (int sj = 0; sj < 7; ++sj) {
                float4 v = g_part[((size_t)(si * 32 + 31) * WW + sj * 32 + 31) * D4 + d4];
                if (si < ti && sj < tj) acc4(acc, v);
            }
        g_blockcum[(ti * 8 + tj) * 64 + d4] = acc;
    }
}

// Full SAT(r, c) = tile partial + left strip + above strip + above-left blocks.
__device__ __forceinline__ float4 satval(int r, int c, int d4) {
    int ti = r >> 5, tj = c >> 5;
    float4 v = g_part[((size_t)r * WW + c) * D4 + d4];
    acc4(v, g_rowcum[((ti * 8 + tj) * 32 + (r & 31)) * 64 + d4]);
    acc4(v, g_colcum[((ti * 8 + tj) * 32 + (c & 31)) * 64 + d4]);
    acc4(v, g_blockcum[(ti * 8 + tj) * 64 + d4]);
    return v;
}

// ---------------------------------------------------------------------------
// Gather: 4 boxes per block, 64 float4 lanes per box, <=16 corner loads (L2).
// ---------------------------------------------------------------------------
__global__ void __launch_bounds__(256) roi_gather(const float* __restrict__ boxes,
                                                  float4* __restrict__ out) {
    int n  = blockIdx.x * 4 + (threadIdx.x >> 6);
    int d4 = threadIdx.x & 63;

    float x1 = boxes[n * 4 + 0];
    float y1 = boxes[n * 4 + 1];
    float x2 = boxes[n * 4 + 2];
    float y2 = boxes[n * 4 + 3];

    // _bounds: lo = max(0, floor(lo_f*256)); hi = rint(hi_f*256 + 0.5)
    //          hi = min(256, max(lo+1, hi)). No FMA contraction (match jax).
    int clo = max(0, (int)floorf(__fmul_rn(x1, 256.0f)));
    int chi = (int)rintf(__fadd_rn(__fmul_rn(x2, 256.0f), 0.5f));
    chi = min(WW, max(clo + 1, chi));

    int rlo = max(0, (int)floorf(__fmul_rn(y1, 256.0f)));
    int rhi = (int)rintf(__fadd_rn(__fmul_rn(y2, 256.0f), 0.5f));
    rhi = min(HH, max(rlo + 1, rhi));

    float4 s = satval(rhi - 1, chi - 1, d4);
    if (rlo > 0) {
        float4 a = satval(rlo - 1, chi - 1, d4);
        s.x -= a.x; s.y -= a.y; s.z -= a.z; s.w -= a.w;
    }
    if (clo > 0) {
        float4 bb = satval(rhi - 1, clo - 1, d4);
        s.x -= bb.x; s.y -= bb.y; s.z -= bb.z; s.w -= bb.w;
        if (rlo > 0) acc4(s, satval(rlo - 1, clo - 1, d4));
    }

    float inv = 1.0f / (float)((rhi - rlo) * (chi - clo));
    s.x *= inv; s.y *= inv; s.z *= inv; s.w *= inv;
    out[(size_t)n * D4 + d4] = s;
}

extern "C" void kernel_launch(void* const* d_in, const int* in_sizes, int n_in,
                              void* d_out, int out_size) {
    const float4* feat  = (const float4*)d_in[0];   // (256,256,256) fp32
    const float*  boxes = (const float*)d_in[1];    // (2048,4) fp32
    float4* out = (float4*)d_out;                   // (2048,256) fp32

    const int smem = 32 * RS * 4;                   // 67584 B
    cudaFuncSetAttribute(sat_tile, cudaFuncAttributeMaxDynamicSharedMemorySize, smem);

    sat_tile<<<1024, 256, smem>>>(feat);
    fixups<<<1040, 256>>>();                        // 262144 + 4096 threads
    roi_gather<<<NB / 4, 256>>>(boxes, out);
}